// round 8
// baseline (speedup 1.0000x reference)
#include <cuda_runtime.h>
#include <cuda_bf16.h>
#include <cstdint>

// ---------------------------------------------------------------------------
// SpanClassifier via portable mma.sync bf16x3 (split-fp32) GEMMs.
//   B=8, S=2048, D=256, NREL=129
// Round 8: B-fragment double buffering across ntp groups (LDSM issued one
// group ahead of use), on top of R7's single-barrier cp.async pipeline and
// R6's phase-interleaved MMA order.
// ---------------------------------------------------------------------------

namespace {
constexpr int B_   = 8;
constexpr int S_   = 2048;
constexpr int D_   = 256;
constexpr int NREL = 129;
constexpr int QRS  = 132;
constexpr int BS_  = B_ * S_;   // 16384

constexpr int KC    = 32;                 // k-chunk (bf16 elems)
constexpr int NCH   = D_ / KC;            // 8
constexpr int STRB  = 80;                 // smem row stride bytes (64 data + 16 pad)
constexpr int TILE_B = 128 * STRB;        // 10240 bytes
constexpr int STAGE_B = 4 * TILE_B;       // 40960 bytes (AHI,ALO,BHI,BLO)
constexpr int SMEM_DYN = 2 * STAGE_B;     // 81920 bytes
constexpr int T_AHI = 0;
constexpr int T_ALO = TILE_B;
constexpr int T_BHI = 2 * TILE_B;
constexpr int T_BLO = 3 * TILE_B;
}

// ---------------- scratch (device globals; no runtime allocation) ----------
__device__ __nv_bfloat16 g_Xhi[BS_ * D_];
__device__ __nv_bfloat16 g_Xlo[BS_ * D_];
__device__ __nv_bfloat16 g_Phi[4][BS_ * D_];
__device__ __nv_bfloat16 g_Plo[4][BS_ * D_];
__device__ __nv_bfloat16 g_Whi[4][D_ * D_];
__device__ __nv_bfloat16 g_Wlo[4][D_ * D_];
__device__ __nv_bfloat16 g_Rhi[2][NREL * D_];
__device__ __nv_bfloat16 g_Rlo[2][NREL * D_];
__device__ float g_QR[2][BS_ * QRS];

// ---------------- PTX helpers ----------------------------------------------
__device__ __forceinline__ uint32_t smem_u32(const void* p) {
    uint32_t a;
    asm("{ .reg .u64 t; cvta.to.shared.u64 t, %1; cvt.u32.u64 %0, t; }"
        : "=r"(a) : "l"(p));
    return a;
}

#define LDSM4(R, addr)                                                        \
    asm volatile("ldmatrix.sync.aligned.m8n8.x4.shared.b16 {%0,%1,%2,%3}, [%4];" \
                 : "=r"((R)[0]), "=r"((R)[1]), "=r"((R)[2]), "=r"((R)[3])     \
                 : "r"(addr))

#define MMA_BF16(C, A, B0, B1)                                                \
    asm volatile("mma.sync.aligned.m16n8k16.row.col.f32.bf16.bf16.f32 "       \
                 "{%0,%1,%2,%3},{%4,%5,%6,%7},{%8,%9},{%0,%1,%2,%3};"         \
                 : "+f"((C)[0]), "+f"((C)[1]), "+f"((C)[2]), "+f"((C)[3])     \
                 : "r"((A)[0]), "r"((A)[1]), "r"((A)[2]), "r"((A)[3]),        \
                   "r"(B0), "r"(B1))

__device__ __forceinline__ void cp16(uint32_t dst, const void* src, bool valid) {
    uint32_t n = valid ? 16u : 0u;
    asm volatile("cp.async.cg.shared.global [%0], [%1], 16, %2;"
                 :: "r"(dst), "l"(src), "r"(n));
}
#define CP_COMMIT() asm volatile("cp.async.commit_group;" ::: "memory")
#define CP_WAIT0()  asm volatile("cp.async.wait_group 0;" ::: "memory")

// ---------------- stage prefetch: 4 tiles of [128 x 32] bf16 ---------------
__device__ __forceinline__ void prefetch_stage(
    uint32_t smstage,
    const __nv_bfloat16* __restrict__ Ahi, const __nv_bfloat16* __restrict__ Alo,
    const __nv_bfloat16* __restrict__ Bhi, const __nv_bfloat16* __restrict__ Blo,
    int rowA0, int rowB0, int bLim, int col0, int tid)
{
#pragma unroll
    for (int t = 0; t < 2; t++) {
        const int idx = t * 256 + tid;     // 0..511
        const int r   = idx >> 2;          // 0..127
        const int c4  = idx & 3;           // 16B group
        const uint32_t so = (uint32_t)(r * STRB + c4 * 16);
        const size_t gao = (size_t)(rowA0 + r) * D_ + col0 + c4 * 8;
        cp16(smstage + T_AHI + so, Ahi + gao, true);
        cp16(smstage + T_ALO + so, Alo + gao, true);
        const bool bv = (rowB0 + r) < bLim;
        const int gbr = bv ? (rowB0 + r) : 0;
        const size_t gbo = (size_t)gbr * D_ + col0 + c4 * 8;
        cp16(smstage + T_BHI + so, Bhi + gbo, bv);
        cp16(smstage + T_BLO + so, Blo + gbo, bv);
    }
}

// ---------------- GEMM core: acc[2][8][4] = A[128,256] * B^T ---------------
// Warp grid 4x2 (m x n): warp computes 32x64 via 2x8 m16n8k16 tiles.
extern __shared__ char dynsm[];

__device__ __forceinline__ void gemm_mma(
    const __nv_bfloat16* __restrict__ Ahi, const __nv_bfloat16* __restrict__ Alo,
    const __nv_bfloat16* __restrict__ Bhi, const __nv_bfloat16* __restrict__ Blo,
    int rowA0, int rowB0, int bLim, float acc[2][8][4])
{
    const int tid  = threadIdx.x;
    const int lane = tid & 31;
    const int wid  = tid >> 5;
    const int mw   = wid >> 1;   // 0..3
    const int nw   = wid & 1;    // 0..1

    const uint32_t smb = smem_u32(dynsm);

    const int lrow       = lane & 15;
    const uint32_t khalf = (uint32_t)((lane >> 4) * 16);

    const uint32_t aOff = (uint32_t)((mw * 32 + lrow) * STRB) + khalf;
    const uint32_t bOff = (uint32_t)((nw * 64 + lrow) * STRB) + khalf;

#pragma unroll
    for (int mt = 0; mt < 2; mt++)
#pragma unroll
        for (int nt = 0; nt < 8; nt++)
#pragma unroll
            for (int e = 0; e < 4; e++) acc[mt][nt][e] = 0.f;

    prefetch_stage(smb, Ahi, Alo, Bhi, Blo, rowA0, rowB0, bLim, 0, tid);
    CP_COMMIT();

    for (int c = 0; c < NCH; c++) {
        CP_WAIT0();
        __syncthreads();   // publishes chunk c; also guards stage reuse

        if (c + 1 < NCH) {
            prefetch_stage(smb + ((c + 1) & 1) * STAGE_B, Ahi, Alo, Bhi, Blo,
                           rowA0, rowB0, bLim, (c + 1) * KC, tid);
            CP_COMMIT();
        }

        const uint32_t aHi = smb + (c & 1) * STAGE_B + T_AHI + aOff;
        const uint32_t bHi = smb + (c & 1) * STAGE_B + T_BHI + bOff;
        // lo tiles live exactly TILE_B after the hi tiles

#pragma unroll
        for (int ks = 0; ks < 2; ks++) {
            const uint32_t ko = (uint32_t)(ks * 32);
            uint32_t ah[2][4], al[2][4];
#pragma unroll
            for (int mt = 0; mt < 2; mt++) {
                LDSM4(ah[mt], aHi + (uint32_t)(mt * 16 * STRB) + ko);
                LDSM4(al[mt], aHi + (uint32_t)(TILE_B + mt * 16 * STRB) + ko);
            }
            // B double buffer: issue ntp+1's loads before ntp's MMAs.
            uint32_t bh[2][4], bl[2][4];
            LDSM4(bh[0], bHi + ko);
            LDSM4(bl[0], bHi + (uint32_t)TILE_B + ko);
#pragma unroll
            for (int ntp = 0; ntp < 4; ntp++) {
                const int cur = ntp & 1, nxt = cur ^ 1;
                if (ntp < 3) {
                    const uint32_t nb = (uint32_t)((ntp + 1) * 16 * STRB) + ko;
                    LDSM4(bh[nxt], bHi + nb);
                    LDSM4(bl[nxt], bHi + (uint32_t)TILE_B + nb);
                }
                const int nt0 = ntp * 2, nt1 = nt0 + 1;
                // Phase-interleaved: same-accumulator MMAs separated by 3.
                MMA_BF16(acc[0][nt0], ah[0], bh[cur][0], bh[cur][2]);
                MMA_BF16(acc[1][nt0], ah[1], bh[cur][0], bh[cur][2]);
                MMA_BF16(acc[0][nt1], ah[0], bh[cur][1], bh[cur][3]);
                MMA_BF16(acc[1][nt1], ah[1], bh[cur][1], bh[cur][3]);
                MMA_BF16(acc[0][nt0], ah[0], bl[cur][0], bl[cur][2]);
                MMA_BF16(acc[1][nt0], ah[1], bl[cur][0], bl[cur][2]);
                MMA_BF16(acc[0][nt1], ah[0], bl[cur][1], bl[cur][3]);
                MMA_BF16(acc[1][nt1], ah[1], bl[cur][1], bl[cur][3]);
                MMA_BF16(acc[0][nt0], al[0], bh[cur][0], bh[cur][2]);
                MMA_BF16(acc[1][nt0], al[1], bh[cur][0], bh[cur][2]);
                MMA_BF16(acc[0][nt1], al[0], bh[cur][1], bh[cur][3]);
                MMA_BF16(acc[1][nt1], al[1], bh[cur][1], bh[cur][3]);
            }
        }
    }
}

// Fragment -> (row, col): row = mw*32 + mt*16 + (lane>>2) + 8*h ;
// col = nw*64 + nt*8 + (lane&3)*2 + {0,1} ; acc element e = h*2 + {0,1}.

// ---------------- 0) converts ------------------------------------------------
__device__ __forceinline__ void split_store(float x, __nv_bfloat16* hi,
                                            __nv_bfloat16* lo, size_t i)
{
    __nv_bfloat16 h = __float2bfloat16(x);
    hi[i] = h;
    lo[i] = __float2bfloat16(x - __bfloat162float(h));
}

__global__ void convert_x_kernel(const float* __restrict__ src) {
    const int i4 = blockIdx.x * 256 + threadIdx.x;
    const size_t i = (size_t)i4 * 4;
    if (i + 3 < (size_t)BS_ * D_) {
        float4 v = *(const float4*)(src + i);
        __nv_bfloat16 h0 = __float2bfloat16(v.x), h1 = __float2bfloat16(v.y);
        __nv_bfloat16 h2 = __float2bfloat16(v.z), h3 = __float2bfloat16(v.w);
        __nv_bfloat162 hp0(h0, h1), hp1(h2, h3);
        __nv_bfloat162 lp0(__float2bfloat16(v.x - __bfloat162float(h0)),
                           __float2bfloat16(v.y - __bfloat162float(h1)));
        __nv_bfloat162 lp1(__float2bfloat16(v.z - __bfloat162float(h2)),
                           __float2bfloat16(v.w - __bfloat162float(h3)));
        *(__nv_bfloat162*)(g_Xhi + i)     = hp0;
        *(__nv_bfloat162*)(g_Xhi + i + 2) = hp1;
        *(__nv_bfloat162*)(g_Xlo + i)     = lp0;
        *(__nv_bfloat162*)(g_Xlo + i + 2) = lp1;
    }
}

__global__ void convert_small_kernel(
    const float* __restrict__ w0, const float* __restrict__ w1,
    const float* __restrict__ w2, const float* __restrict__ w3,
    const float* __restrict__ r0, const float* __restrict__ r1)
{
    const int z = blockIdx.y;
    const float* src;
    __nv_bfloat16 *hi, *lo;
    int n;
    if (z < 4) {
        src = (z == 0) ? w0 : (z == 1) ? w1 : (z == 2) ? w2 : w3;
        hi = g_Whi[z]; lo = g_Wlo[z]; n = D_ * D_;
    } else {
        src = (z == 4) ? r0 : r1;
        hi = g_Rhi[z - 4]; lo = g_Rlo[z - 4]; n = NREL * D_;
    }
    int i = blockIdx.x * 256 + threadIdx.x;
    if (i < n) split_store(src[i], hi, lo, i);
}

// ---------------- 1) projections --------------------------------------------
__global__ void __launch_bounds__(256, 2)
proj_kernel(const float* __restrict__ bq1, const float* __restrict__ bk1,
            const float* __restrict__ bq2, const float* __restrict__ bk2)
{
    const int z = blockIdx.z;
    const float* bias = (z == 0) ? bq1 : (z == 1) ? bk1 : (z == 2) ? bq2 : bk2;
    const float scale = (z == 0 || z == 2) ? 0.0625f : 1.0f;

    const int mBase = blockIdx.y * 128;
    const int nBase = blockIdx.x * 128;

    float acc[2][8][4];
    gemm_mma(g_Xhi, g_Xlo, g_Whi[z], g_Wlo[z], mBase, nBase, 1 << 30, acc);

    const int lane = threadIdx.x & 31, wid = threadIdx.x >> 5;
    const int mw = wid >> 1, nw = wid & 1;

#pragma unroll
    for (int mt = 0; mt < 2; mt++) {
#pragma unroll
        for (int h = 0; h < 2; h++) {
            const int m = mBase + mw * 32 + mt * 16 + (lane >> 2) + 8 * h;
            __nv_bfloat16* dhi = g_Phi[z] + (size_t)m * D_;
            __nv_bfloat16* dlo = g_Plo[z] + (size_t)m * D_;
#pragma unroll
            for (int nt = 0; nt < 8; nt++) {
                const int col = nBase + nw * 64 + nt * 8 + (lane & 3) * 2;
                float y0 = (acc[mt][nt][h * 2 + 0] + bias[col + 0]) * scale;
                float y1 = (acc[mt][nt][h * 2 + 1] + bias[col + 1]) * scale;
                __nv_bfloat16 h0 = __float2bfloat16(y0);
                __nv_bfloat16 h1 = __float2bfloat16(y1);
                __nv_bfloat162 hp(h0, h1);
                __nv_bfloat162 lp(__float2bfloat16(y0 - __bfloat162float(h0)),
                                  __float2bfloat16(y1 - __bfloat162float(h1)));
                *(__nv_bfloat162*)(dhi + col) = hp;
                *(__nv_bfloat162*)(dlo + col) = lp;
            }
        }
    }
}

// ---------------- 2) q_rel: cols 0..127 via GEMM -----------------------------
__global__ void __launch_bounds__(256, 2)
qr_kernel()
{
    const int head  = blockIdx.z;
    const int mBase = blockIdx.y * 128;

    float acc[2][8][4];
    gemm_mma(g_Phi[head * 2], g_Plo[head * 2], g_Rhi[head], g_Rlo[head],
             mBase, 0, 128, acc);

    const int lane = threadIdx.x & 31, wid = threadIdx.x >> 5;
    const int mw = wid >> 1, nw = wid & 1;

#pragma unroll
    for (int mt = 0; mt < 2; mt++) {
#pragma unroll
        for (int h = 0; h < 2; h++) {
            const int m = mBase + mw * 32 + mt * 16 + (lane >> 2) + 8 * h;
            float* dst = g_QR[head] + (size_t)m * QRS;
#pragma unroll
            for (int nt = 0; nt < 8; nt++) {
                const int col = nw * 64 + nt * 8 + (lane & 3) * 2;
                *(float2*)(dst + col) =
                    make_float2(acc[mt][nt][h * 2 + 0], acc[mt][nt][h * 2 + 1]);
            }
        }
    }
}

// ---------------- 2b) q_rel column 128 (rel position +64) via GEMV ----------
__global__ void __launch_bounds__(256)
qr_col_kernel()
{
    const int gw   = blockIdx.x * 8 + (threadIdx.x >> 5);  // 0..2047
    const int lane = threadIdx.x & 31;
    const int head = gw >> 10;
    const int row0 = (gw & 1023) * 16;

    float rf[8];
    {
        const __nv_bfloat16* rh = g_Rhi[head] + (size_t)128 * D_ + lane * 8;
        const __nv_bfloat16* rl = g_Rlo[head] + (size_t)128 * D_ + lane * 8;
        uint4 vh = *(const uint4*)rh;
        uint4 vl = *(const uint4*)rl;
        const __nv_bfloat16* ph = (const __nv_bfloat16*)&vh;
        const __nv_bfloat16* pl = (const __nv_bfloat16*)&vl;
#pragma unroll
        for (int j = 0; j < 8; j++)
            rf[j] = __bfloat162float(ph[j]) + __bfloat162float(pl[j]);
    }

    const __nv_bfloat16* Qhi = g_Phi[head * 2];
    const __nv_bfloat16* Qlo = g_Plo[head * 2];

    for (int r = 0; r < 16; r++) {
        const int row = row0 + r;
        uint4 vh = *(const uint4*)(Qhi + (size_t)row * D_ + lane * 8);
        uint4 vl = *(const uint4*)(Qlo + (size_t)row * D_ + lane * 8);
        const __nv_bfloat16* ph = (const __nv_bfloat16*)&vh;
        const __nv_bfloat16* pl = (const __nv_bfloat16*)&vl;
        float s = 0.f;
#pragma unroll
        for (int j = 0; j < 8; j++)
            s += (__bfloat162float(ph[j]) + __bfloat162float(pl[j])) * rf[j];
#pragma unroll
        for (int o = 16; o > 0; o >>= 1)
            s += __shfl_xor_sync(0xFFFFFFFF, s, o);
        if (lane == 0) g_QR[head][(size_t)row * QRS + 128] = s;
    }
}

// ---------------- 3) scores ---------------------------------------------------
__global__ void __launch_bounds__(256, 2)
scores_kernel(const int* __restrict__ mask, float* __restrict__ out)
{
    const int z    = blockIdx.z;
    const int head = z >> 3;
    const int b    = z & 7;
    const int qBase = blockIdx.y * 128;
    const int kBase = blockIdx.x * 128;

    const size_t po = (size_t)b * S_ * D_;
    float acc[2][8][4];
    gemm_mma(g_Phi[head * 2 + 0] + po, g_Plo[head * 2 + 0] + po,
             g_Phi[head * 2 + 1] + po, g_Plo[head * 2 + 1] + po,
             qBase, kBase, 1 << 30, acc);

    const int lane = threadIdx.x & 31, wid = threadIdx.x >> 5;
    const int mw = wid >> 1, nw = wid & 1;
    const int* mrow = mask + b * S_;

#pragma unroll
    for (int mt = 0; mt < 2; mt++) {
#pragma unroll
        for (int h = 0; h < 2; h++) {
            const int qg = qBase + mw * 32 + mt * 16 + (lane >> 2) + 8 * h;
            const int mq = mrow[qg];
            const float* qr = g_QR[head] + ((size_t)b * S_ + qg) * QRS;
            float* orow = out + (((size_t)head * B_ + b) * S_ + qg) * S_;
#pragma unroll
            for (int nt = 0; nt < 8; nt++) {
                const int kg = kBase + nw * 64 + nt * 8 + (lane & 3) * 2;
                int d0 = kg - qg;
                int d1 = d0 + 1;
                d0 = (d0 < -64) ? -64 : ((d0 > 64) ? 64 : d0);
                d1 = (d1 < -64) ? -64 : ((d1 > 64) ? 64 : d1);
                float v0 = acc[mt][nt][h * 2 + 0] + qr[d0 + 64];
                float v1 = acc[mt][nt][h * 2 + 1] + qr[d1 + 64];
                if (mq == 0 || mrow[kg + 0] == 0) v0 = -1e18f;
                if (mq == 0 || mrow[kg + 1] == 0) v1 = -1e18f;
                float2 v = make_float2(v0, v1);
                *(float2*)(orow + kg) = v;
            }
        }
    }
}

// ---------------- launch -------------------------------------------------------
extern "C" void kernel_launch(void* const* d_in, const int* in_sizes, int n_in,
                              void* d_out, int out_size)
{
    const float* repre = (const float*)d_in[0];
    const int*   mask  = (const int*)d_in[1];
    const float* wq1 = (const float*)d_in[2];
    const float* bq1 = (const float*)d_in[3];
    const float* wk1 = (const float*)d_in[4];
    const float* bk1 = (const float*)d_in[5];
    const float* rel1 = (const float*)d_in[6];
    const float* wq2 = (const float*)d_in[7];
    const float* bq2 = (const float*)d_in[8];
    const float* wk2 = (const float*)d_in[9];
    const float* bk2 = (const float*)d_in[10];
    const float* rel2 = (const float*)d_in[11];
    float* out = (float*)d_out;
    (void)in_sizes; (void)n_in; (void)out_size;

    cudaFuncSetAttribute(proj_kernel,
                         cudaFuncAttributeMaxDynamicSharedMemorySize, SMEM_DYN);
    cudaFuncSetAttribute(qr_kernel,
                         cudaFuncAttributeMaxDynamicSharedMemorySize, SMEM_DYN);
    cudaFuncSetAttribute(scores_kernel,
                         cudaFuncAttributeMaxDynamicSharedMemorySize, SMEM_DYN);

    const int NX4 = BS_ * D_ / 4;
    const int NW = D_ * D_;

    convert_x_kernel<<<(NX4 + 255) / 256, 256>>>(repre);
    convert_small_kernel<<<dim3((NW + 255) / 256, 6), 256>>>(
        wq1, wk1, wq2, wk2, rel1, rel2);

    proj_kernel<<<dim3(2, 128, 4), 256, SMEM_DYN>>>(bq1, bk1, bq2, bk2);
    qr_kernel<<<dim3(1, 128, 2), 256, SMEM_DYN>>>();
    qr_col_kernel<<<256, 256>>>();
    scores_kernel<<<dim3(16, 16, 16), 256, SMEM_DYN>>>(mask, out);
}

// round 9
// speedup vs baseline: 1.2296x; 1.2296x over previous
#include <cuda_runtime.h>
#include <cuda_fp16.h>
#include <cstdint>

// ---------------------------------------------------------------------------
// SpanClassifier via portable mma.sync fp16-split GEMMs.
//   B=8, S=2048, D=256, NREL=129
// Round 9: fp16 (11-bit mantissa) hi/lo split instead of bf16.
//   proj:       3 MMAs (hi*hi + hi*lo + lo*hi)  -> error ~2^-22
//   qr/scores:  2 MMAs (hi*hi + hi_A*lo_B)      -> error ~2^-11 ≈ 5e-4 rel
// Scores kernel does 33% less tensor work and 25% less cp.async traffic
// (A-lo tile never touched). Mainloop is R7's single-barrier pipeline with
// phase-interleaved MMA issue.
// ---------------------------------------------------------------------------

namespace {
constexpr int B_   = 8;
constexpr int S_   = 2048;
constexpr int D_   = 256;
constexpr int NREL = 129;
constexpr int QRS  = 132;
constexpr int BS_  = B_ * S_;   // 16384

constexpr int KC    = 32;                 // k-chunk (fp16 elems)
constexpr int NCH   = D_ / KC;            // 8
constexpr int STRB  = 80;                 // smem row stride bytes (64 data + 16 pad)
constexpr int TILE_B = 128 * STRB;        // 10240 bytes
constexpr int STAGE_B = 4 * TILE_B;       // 40960 bytes (AHI,ALO,BHI,BLO)
constexpr int SMEM_DYN = 2 * STAGE_B;     // 81920 bytes
constexpr int T_AHI = 0;
constexpr int T_ALO = TILE_B;
constexpr int T_BHI = 2 * TILE_B;
constexpr int T_BLO = 3 * TILE_B;
}

// ---------------- scratch (device globals; no runtime allocation) ----------
__device__ __half g_Xhi[BS_ * D_];
__device__ __half g_Xlo[BS_ * D_];
__device__ __half g_Phi[4][BS_ * D_];
__device__ __half g_Plo[4][BS_ * D_];
__device__ __half g_Whi[4][D_ * D_];
__device__ __half g_Wlo[4][D_ * D_];
__device__ __half g_Rhi[2][NREL * D_];
__device__ __half g_Rlo[2][NREL * D_];
__device__ float g_QR[2][BS_ * QRS];

// ---------------- PTX helpers ----------------------------------------------
__device__ __forceinline__ uint32_t smem_u32(const void* p) {
    uint32_t a;
    asm("{ .reg .u64 t; cvta.to.shared.u64 t, %1; cvt.u32.u64 %0, t; }"
        : "=r"(a) : "l"(p));
    return a;
}

#define LDSM4(R, addr)                                                        \
    asm volatile("ldmatrix.sync.aligned.m8n8.x4.shared.b16 {%0,%1,%2,%3}, [%4];" \
                 : "=r"((R)[0]), "=r"((R)[1]), "=r"((R)[2]), "=r"((R)[3])     \
                 : "r"(addr))

#define MMA_F16(C, A, B0, B1)                                                 \
    asm volatile("mma.sync.aligned.m16n8k16.row.col.f32.f16.f16.f32 "         \
                 "{%0,%1,%2,%3},{%4,%5,%6,%7},{%8,%9},{%0,%1,%2,%3};"         \
                 : "+f"((C)[0]), "+f"((C)[1]), "+f"((C)[2]), "+f"((C)[3])     \
                 : "r"((A)[0]), "r"((A)[1]), "r"((A)[2]), "r"((A)[3]),        \
                   "r"(B0), "r"(B1))

__device__ __forceinline__ void cp16(uint32_t dst, const void* src, bool valid) {
    uint32_t n = valid ? 16u : 0u;
    asm volatile("cp.async.cg.shared.global [%0], [%1], 16, %2;"
                 :: "r"(dst), "l"(src), "r"(n));
}
#define CP_COMMIT() asm volatile("cp.async.commit_group;" ::: "memory")
#define CP_WAIT0()  asm volatile("cp.async.wait_group 0;" ::: "memory")

// ---------------- stage prefetch ---------------------------------------------
// THREE=true loads AHI/ALO/BHI/BLO; THREE=false skips ALO.
template <bool THREE>
__device__ __forceinline__ void prefetch_stage(
    uint32_t smstage,
    const __half* __restrict__ Ahi, const __half* __restrict__ Alo,
    const __half* __restrict__ Bhi, const __half* __restrict__ Blo,
    int rowA0, int rowB0, int bLim, int col0, int tid)
{
#pragma unroll
    for (int t = 0; t < 2; t++) {
        const int idx = t * 256 + tid;     // 0..511
        const int r   = idx >> 2;          // 0..127
        const int c4  = idx & 3;           // 16B group
        const uint32_t so = (uint32_t)(r * STRB + c4 * 16);
        const size_t gao = (size_t)(rowA0 + r) * D_ + col0 + c4 * 8;
        cp16(smstage + T_AHI + so, Ahi + gao, true);
        if (THREE)
            cp16(smstage + T_ALO + so, Alo + gao, true);
        const bool bv = (rowB0 + r) < bLim;
        const int gbr = bv ? (rowB0 + r) : 0;
        const size_t gbo = (size_t)gbr * D_ + col0 + c4 * 8;
        cp16(smstage + T_BHI + so, Bhi + gbo, bv);
        cp16(smstage + T_BLO + so, Blo + gbo, bv);
    }
}

// ---------------- GEMM core: acc[2][8][4] = A[128,256] * B^T -----------------
// Warp grid 4x2 (m x n): warp computes 32x64 via 2x8 m16n8k16 tiles.
// THREE=true:  hi*hi + hi*lo + lo*hi (12 MMAs/ntp group)
// THREE=false: hi*hi + hi_A*lo_B     (8 MMAs/ntp group, A-lo untouched)
extern __shared__ char dynsm[];

template <bool THREE>
__device__ __forceinline__ void gemm_mma(
    const __half* __restrict__ Ahi, const __half* __restrict__ Alo,
    const __half* __restrict__ Bhi, const __half* __restrict__ Blo,
    int rowA0, int rowB0, int bLim, float acc[2][8][4])
{
    const int tid  = threadIdx.x;
    const int lane = tid & 31;
    const int wid  = tid >> 5;
    const int mw   = wid >> 1;   // 0..3
    const int nw   = wid & 1;    // 0..1

    const uint32_t smb = smem_u32(dynsm);

    const int lrow       = lane & 15;
    const uint32_t khalf = (uint32_t)((lane >> 4) * 16);

    const uint32_t aOff = (uint32_t)((mw * 32 + lrow) * STRB) + khalf;
    const uint32_t bOff = (uint32_t)((nw * 64 + lrow) * STRB) + khalf;

#pragma unroll
    for (int mt = 0; mt < 2; mt++)
#pragma unroll
        for (int nt = 0; nt < 8; nt++)
#pragma unroll
            for (int e = 0; e < 4; e++) acc[mt][nt][e] = 0.f;

    prefetch_stage<THREE>(smb, Ahi, Alo, Bhi, Blo, rowA0, rowB0, bLim, 0, tid);
    CP_COMMIT();

    for (int c = 0; c < NCH; c++) {
        CP_WAIT0();
        __syncthreads();   // publishes chunk c; guards stage reuse

        if (c + 1 < NCH) {
            prefetch_stage<THREE>(smb + ((c + 1) & 1) * STAGE_B, Ahi, Alo,
                                  Bhi, Blo, rowA0, rowB0, bLim,
                                  (c + 1) * KC, tid);
            CP_COMMIT();
        }

        const uint32_t st = smb + (c & 1) * STAGE_B;
        const uint32_t aHi = st + T_AHI + aOff;
        const uint32_t bHi = st + T_BHI + bOff;

#pragma unroll
        for (int ks = 0; ks < 2; ks++) {
            const uint32_t ko = (uint32_t)(ks * 32);
            uint32_t ah[2][4], al[2][4];
#pragma unroll
            for (int mt = 0; mt < 2; mt++) {
                LDSM4(ah[mt], aHi + (uint32_t)(mt * 16 * STRB) + ko);
                if (THREE)
                    LDSM4(al[mt], aHi + (uint32_t)(TILE_B + mt * 16 * STRB) + ko);
            }
#pragma unroll
            for (int ntp = 0; ntp < 4; ntp++) {
                uint32_t bh[4], bl[4];
                const uint32_t nb = (uint32_t)(ntp * 16 * STRB) + ko;
                LDSM4(bh, bHi + nb);
                LDSM4(bl, bHi + (uint32_t)TILE_B + nb);
                const int nt0 = ntp * 2, nt1 = nt0 + 1;
                // Phase-interleaved: same-accumulator MMAs separated by 3.
                MMA_F16(acc[0][nt0], ah[0], bh[0], bh[2]);
                MMA_F16(acc[1][nt0], ah[1], bh[0], bh[2]);
                MMA_F16(acc[0][nt1], ah[0], bh[1], bh[3]);
                MMA_F16(acc[1][nt1], ah[1], bh[1], bh[3]);
                MMA_F16(acc[0][nt0], ah[0], bl[0], bl[2]);
                MMA_F16(acc[1][nt0], ah[1], bl[0], bl[2]);
                MMA_F16(acc[0][nt1], ah[0], bl[1], bl[3]);
                MMA_F16(acc[1][nt1], ah[1], bl[1], bl[3]);
                if (THREE) {
                    MMA_F16(acc[0][nt0], al[0], bh[0], bh[2]);
                    MMA_F16(acc[1][nt0], al[1], bh[0], bh[2]);
                    MMA_F16(acc[0][nt1], al[0], bh[1], bh[3]);
                    MMA_F16(acc[1][nt1], al[1], bh[1], bh[3]);
                }
            }
        }
    }
}

// Fragment -> (row, col): row = mw*32 + mt*16 + (lane>>2) + 8*h ;
// col = nw*64 + nt*8 + (lane&3)*2 + {0,1} ; acc element e = h*2 + {0,1}.

// ---------------- 0) converts -------------------------------------------------
__device__ __forceinline__ void split_store(float x, __half* hi,
                                            __half* lo, size_t i)
{
    __half h = __float2half_rn(x);
    hi[i] = h;
    lo[i] = __float2half_rn(x - __half2float(h));
}

__global__ void convert_x_kernel(const float* __restrict__ src) {
    const int i4 = blockIdx.x * 256 + threadIdx.x;
    const size_t i = (size_t)i4 * 4;
    if (i + 3 < (size_t)BS_ * D_) {
        float4 v = *(const float4*)(src + i);
        __half h0 = __float2half_rn(v.x), h1 = __float2half_rn(v.y);
        __half h2 = __float2half_rn(v.z), h3 = __float2half_rn(v.w);
        __half2 hp0 = __halves2half2(h0, h1), hp1 = __halves2half2(h2, h3);
        __half2 lp0 = __halves2half2(__float2half_rn(v.x - __half2float(h0)),
                                     __float2half_rn(v.y - __half2float(h1)));
        __half2 lp1 = __halves2half2(__float2half_rn(v.z - __half2float(h2)),
                                     __float2half_rn(v.w - __half2float(h3)));
        *(__half2*)(g_Xhi + i)     = hp0;
        *(__half2*)(g_Xhi + i + 2) = hp1;
        *(__half2*)(g_Xlo + i)     = lp0;
        *(__half2*)(g_Xlo + i + 2) = lp1;
    }
}

__global__ void convert_small_kernel(
    const float* __restrict__ w0, const float* __restrict__ w1,
    const float* __restrict__ w2, const float* __restrict__ w3,
    const float* __restrict__ r0, const float* __restrict__ r1)
{
    const int z = blockIdx.y;
    const float* src;
    __half *hi, *lo;
    int n;
    if (z < 4) {
        src = (z == 0) ? w0 : (z == 1) ? w1 : (z == 2) ? w2 : w3;
        hi = g_Whi[z]; lo = g_Wlo[z]; n = D_ * D_;
    } else {
        src = (z == 4) ? r0 : r1;
        hi = g_Rhi[z - 4]; lo = g_Rlo[z - 4]; n = NREL * D_;
    }
    int i = blockIdx.x * 256 + threadIdx.x;
    if (i < n) split_store(src[i], hi, lo, i);
}

// ---------------- 1) projections (full 3-MMA precision) ----------------------
__global__ void __launch_bounds__(256, 2)
proj_kernel(const float* __restrict__ bq1, const float* __restrict__ bk1,
            const float* __restrict__ bq2, const float* __restrict__ bk2)
{
    const int z = blockIdx.z;
    const float* bias = (z == 0) ? bq1 : (z == 1) ? bk1 : (z == 2) ? bq2 : bk2;
    const float scale = (z == 0 || z == 2) ? 0.0625f : 1.0f;

    const int mBase = blockIdx.y * 128;
    const int nBase = blockIdx.x * 128;

    float acc[2][8][4];
    gemm_mma<true>(g_Xhi, g_Xlo, g_Whi[z], g_Wlo[z], mBase, nBase, 1 << 30, acc);

    const int lane = threadIdx.x & 31, wid = threadIdx.x >> 5;
    const int mw = wid >> 1, nw = wid & 1;

#pragma unroll
    for (int mt = 0; mt < 2; mt++) {
#pragma unroll
        for (int h = 0; h < 2; h++) {
            const int m = mBase + mw * 32 + mt * 16 + (lane >> 2) + 8 * h;
            __half* dhi = g_Phi[z] + (size_t)m * D_;
            __half* dlo = g_Plo[z] + (size_t)m * D_;
#pragma unroll
            for (int nt = 0; nt < 8; nt++) {
                const int col = nBase + nw * 64 + nt * 8 + (lane & 3) * 2;
                float y0 = (acc[mt][nt][h * 2 + 0] + bias[col + 0]) * scale;
                float y1 = (acc[mt][nt][h * 2 + 1] + bias[col + 1]) * scale;
                __half h0 = __float2half_rn(y0);
                __half h1 = __float2half_rn(y1);
                __half2 hp = __halves2half2(h0, h1);
                __half2 lp = __halves2half2(
                    __float2half_rn(y0 - __half2float(h0)),
                    __float2half_rn(y1 - __half2float(h1)));
                *(__half2*)(dhi + col) = hp;
                *(__half2*)(dlo + col) = lp;
            }
        }
    }
}

// ---------------- 2) q_rel: cols 0..127 via GEMM (2-MMA) ---------------------
__global__ void __launch_bounds__(256, 2)
qr_kernel()
{
    const int head  = blockIdx.z;
    const int mBase = blockIdx.y * 128;

    float acc[2][8][4];
    gemm_mma<false>(g_Phi[head * 2], g_Plo[head * 2], g_Rhi[head], g_Rlo[head],
                    mBase, 0, 128, acc);

    const int lane = threadIdx.x & 31, wid = threadIdx.x >> 5;
    const int mw = wid >> 1, nw = wid & 1;

#pragma unroll
    for (int mt = 0; mt < 2; mt++) {
#pragma unroll
        for (int h = 0; h < 2; h++) {
            const int m = mBase + mw * 32 + mt * 16 + (lane >> 2) + 8 * h;
            float* dst = g_QR[head] + (size_t)m * QRS;
#pragma unroll
            for (int nt = 0; nt < 8; nt++) {
                const int col = nw * 64 + nt * 8 + (lane & 3) * 2;
                *(float2*)(dst + col) =
                    make_float2(acc[mt][nt][h * 2 + 0], acc[mt][nt][h * 2 + 1]);
            }
        }
    }
}

// ---------------- 2b) q_rel column 128 (rel position +64) via GEMV -----------
__global__ void __launch_bounds__(256)
qr_col_kernel()
{
    const int gw   = blockIdx.x * 8 + (threadIdx.x >> 5);  // 0..2047
    const int lane = threadIdx.x & 31;
    const int head = gw >> 10;
    const int row0 = (gw & 1023) * 16;

    float rf[8];
    {
        const __half* rh = g_Rhi[head] + (size_t)128 * D_ + lane * 8;
        const __half* rl = g_Rlo[head] + (size_t)128 * D_ + lane * 8;
        uint4 vh = *(const uint4*)rh;
        uint4 vl = *(const uint4*)rl;
        const __half* ph = (const __half*)&vh;
        const __half* pl = (const __half*)&vl;
#pragma unroll
        for (int j = 0; j < 8; j++)
            rf[j] = __half2float(ph[j]) + __half2float(pl[j]);
    }

    const __half* Qhi = g_Phi[head * 2];
    const __half* Qlo = g_Plo[head * 2];

    for (int r = 0; r < 16; r++) {
        const int row = row0 + r;
        uint4 vh = *(const uint4*)(Qhi + (size_t)row * D_ + lane * 8);
        uint4 vl = *(const uint4*)(Qlo + (size_t)row * D_ + lane * 8);
        const __half* ph = (const __half*)&vh;
        const __half* pl = (const __half*)&vl;
        float s = 0.f;
#pragma unroll
        for (int j = 0; j < 8; j++)
            s += (__half2float(ph[j]) + __half2float(pl[j])) * rf[j];
#pragma unroll
        for (int o = 16; o > 0; o >>= 1)
            s += __shfl_xor_sync(0xFFFFFFFF, s, o);
        if (lane == 0) g_QR[head][(size_t)row * QRS + 128] = s;
    }
}

// ---------------- 3) scores (2-MMA) ------------------------------------------
__global__ void __launch_bounds__(256, 2)
scores_kernel(const int* __restrict__ mask, float* __restrict__ out)
{
    const int z    = blockIdx.z;
    const int head = z >> 3;
    const int b    = z & 7;
    const int qBase = blockIdx.y * 128;
    const int kBase = blockIdx.x * 128;

    const size_t po = (size_t)b * S_ * D_;
    float acc[2][8][4];
    gemm_mma<false>(g_Phi[head * 2 + 0] + po, g_Plo[head * 2 + 0] + po,
                    g_Phi[head * 2 + 1] + po, g_Plo[head * 2 + 1] + po,
                    qBase, kBase, 1 << 30, acc);

    const int lane = threadIdx.x & 31, wid = threadIdx.x >> 5;
    const int mw = wid >> 1, nw = wid & 1;
    const int* mrow = mask + b * S_;

#pragma unroll
    for (int mt = 0; mt < 2; mt++) {
#pragma unroll
        for (int h = 0; h < 2; h++) {
            const int qg = qBase + mw * 32 + mt * 16 + (lane >> 2) + 8 * h;
            const int mq = mrow[qg];
            const float* qr = g_QR[head] + ((size_t)b * S_ + qg) * QRS;
            float* orow = out + (((size_t)head * B_ + b) * S_ + qg) * S_;
#pragma unroll
            for (int nt = 0; nt < 8; nt++) {
                const int kg = kBase + nw * 64 + nt * 8 + (lane & 3) * 2;
                int d0 = kg - qg;
                int d1 = d0 + 1;
                d0 = (d0 < -64) ? -64 : ((d0 > 64) ? 64 : d0);
                d1 = (d1 < -64) ? -64 : ((d1 > 64) ? 64 : d1);
                float v0 = acc[mt][nt][h * 2 + 0] + qr[d0 + 64];
                float v1 = acc[mt][nt][h * 2 + 1] + qr[d1 + 64];
                if (mq == 0 || mrow[kg + 0] == 0) v0 = -1e18f;
                if (mq == 0 || mrow[kg + 1] == 0) v1 = -1e18f;
                float2 v = make_float2(v0, v1);
                *(float2*)(orow + kg) = v;
            }
        }
    }
}

// ---------------- launch --------------------------------------------------------
extern "C" void kernel_launch(void* const* d_in, const int* in_sizes, int n_in,
                              void* d_out, int out_size)
{
    const float* repre = (const float*)d_in[0];
    const int*   mask  = (const int*)d_in[1];
    const float* wq1 = (const float*)d_in[2];
    const float* bq1 = (const float*)d_in[3];
    const float* wk1 = (const float*)d_in[4];
    const float* bk1 = (const float*)d_in[5];
    const float* rel1 = (const float*)d_in[6];
    const float* wq2 = (const float*)d_in[7];
    const float* bq2 = (const float*)d_in[8];
    const float* wk2 = (const float*)d_in[9];
    const float* bk2 = (const float*)d_in[10];
    const float* rel2 = (const float*)d_in[11];
    float* out = (float*)d_out;
    (void)in_sizes; (void)n_in; (void)out_size;

    cudaFuncSetAttribute(proj_kernel,
                         cudaFuncAttributeMaxDynamicSharedMemorySize, SMEM_DYN);
    cudaFuncSetAttribute(qr_kernel,
                         cudaFuncAttributeMaxDynamicSharedMemorySize, SMEM_DYN);
    cudaFuncSetAttribute(scores_kernel,
                         cudaFuncAttributeMaxDynamicSharedMemorySize, SMEM_DYN);

    const int NX4 = BS_ * D_ / 4;
    const int NW = D_ * D_;

    convert_x_kernel<<<(NX4 + 255) / 256, 256>>>(repre);
    convert_small_kernel<<<dim3((NW + 255) / 256, 6), 256>>>(
        wq1, wk1, wq2, wk2, rel1, rel2);

    proj_kernel<<<dim3(2, 128, 4), 256, SMEM_DYN>>>(bq1, bk1, bq2, bk2);
    qr_kernel<<<dim3(1, 128, 2), 256, SMEM_DYN>>>();
    qr_col_kernel<<<256, 256>>>();
    scores_kernel<<<dim3(16, 16, 16), 256, SMEM_DYN>>>(mask, out);
}